// round 12
// baseline (speedup 1.0000x reference)
#include <cuda_runtime.h>
#include <cuda_bf16.h>
#include <cstdint>

// Problem constants
#define TT   256     // sequence length
#define BB   32      // batch
#define EMB  256
#define HHD  256     // per-direction hidden
#define G4   1024    // 4*HHD
#define NT   12
#define START_IDX 10
#define STOP_IDX  11
#define BARSTR 32    // barrier slot stride in ints (128B line padding)

typedef unsigned long long ull;

// ---------------- scratch (device globals; no allocation allowed) ----------
__device__ __align__(16) float g_zpre[2L * TT * G4 * BB];   // [dir][t][gate_row][b]
// fp32 h (kept for debug/compat): pair-packed
__device__ __align__(16) float g_hs[2][(TT + 1) * HHD * BB];
// bf16 split h (fragment layout): word wi = slot*8192 + (k>>1)*64 + b*2
//   word wi = {hi(h[2q]), hi(h[2q+1])}, word wi+1 = {lo(h[2q]), lo(h[2q+1])}
__device__ __align__(16) uint32_t g_hsbf[2][(TT + 1) * 8192];
__device__ __align__(16) float g_feats[BB * TT * NT];       // [b][t][tag]
__device__ int   g_bar[2 * TT * BARSTR];                    // padded step counters (target 32)
// bf16 split operands
__device__ __align__(16) __nv_bfloat16 g_Whi[2048 * 256];   // W_ih rows m = dir*1024 + row
__device__ __align__(16) __nv_bfloat16 g_Wlo[2048 * 256];
__device__ __align__(16) __nv_bfloat16 g_Hhi[2048 * 256];   // W_hh rows
__device__ __align__(16) __nv_bfloat16 g_Hlo[2048 * 256];
__device__ __align__(16) __nv_bfloat16 g_xhi[8192 * 256];   // x rows n = t*32 + b
__device__ __align__(16) __nv_bfloat16 g_xlo[8192 * 256];
__device__ __align__(16) __nv_bfloat16 g_Pohi[16 * 512];    // Wout padded (rows 12-15 zero)
__device__ __align__(16) __nv_bfloat16 g_Polo[16 * 512];

// ---------------- generic helpers ------------------------------------------
__device__ __forceinline__ int ldacq(const int* p) {
    int v; asm volatile("ld.acquire.gpu.global.s32 %0, [%1];" : "=r"(v) : "l"(p)); return v;
}
__device__ __forceinline__ void redrel(int* p) {
    asm volatile("red.release.gpu.global.add.s32 [%0], 1;" :: "l"(p));
}
__device__ __forceinline__ void pause_short() {
    uint32_t x = 0;
#pragma unroll
    for (int i = 0; i < 12; i++) asm volatile("add.u32 %0, %0, 1;" : "+r"(x));
}
__device__ __forceinline__ float sigf(float x) {
    float e = __expf(-x);
    return __fdividef(1.0f, 1.0f + e);
}
__device__ __forceinline__ float tanhfast(float x) {
    float ax = fminf(fabsf(x), 15.0f);
    float e = __expf(2.0f * ax);
    float t = __fdividef(e - 1.0f, e + 1.0f);
    return copysignf(t, x);
}
__device__ __forceinline__ uint32_t smem_u32(const void* p) {
    uint32_t a;
    asm("{ .reg .u64 t; cvta.to.shared.u64 t, %1; cvt.u32.u64 %0, t; }" : "=r"(a) : "l"(p));
    return a;
}
__device__ __forceinline__ void ldsm4(uint32_t& r0, uint32_t& r1, uint32_t& r2, uint32_t& r3,
                                      uint32_t addr) {
    asm volatile("ldmatrix.sync.aligned.m8n8.x4.shared.b16 {%0,%1,%2,%3}, [%4];"
                 : "=r"(r0), "=r"(r1), "=r"(r2), "=r"(r3) : "r"(addr));
}
__device__ __forceinline__ void mma16816(float* c, const uint32_t* a, const uint32_t* b) {
    asm volatile("mma.sync.aligned.m16n8k16.row.col.f32.bf16.bf16.f32 "
                 "{%0,%1,%2,%3}, {%4,%5,%6,%7}, {%8,%9}, {%0,%1,%2,%3};"
                 : "+f"(c[0]), "+f"(c[1]), "+f"(c[2]), "+f"(c[3])
                 : "r"(a[0]), "r"(a[1]), "r"(a[2]), "r"(a[3]), "r"(b[0]), "r"(b[1]));
}

// ============================================================================
// K0a: convert W_ih AND W_hh (both dirs) to bf16 hi/lo.  grid 4096.
// ============================================================================
__global__ void k_convW2(const float* __restrict__ Wihf, const float* __restrict__ Wihb,
                         const float* __restrict__ Whhf, const float* __restrict__ Whhb)
{
    int m = blockIdx.x;          // 0..4095
    int k = threadIdx.x;         // 0..255
    const float* src;
    __nv_bfloat16 *dh, *dl;
    int mm;
    if (m < 2048) {
        src = (m < 1024) ? Wihf : Wihb; mm = m;
        dh = g_Whi; dl = g_Wlo;
    } else {
        int m2 = m - 2048;
        src = (m2 < 1024) ? Whhf : Whhb; mm = m2;
        dh = g_Hhi; dl = g_Hlo;
    }
    float v = src[(mm & 1023) * 256 + k];
    __nv_bfloat16 hi = __float2bfloat16(v);
    float r = v - __bfloat162float(hi);
    dh[mm * 256 + k] = hi;
    dl[mm * 256 + k] = __float2bfloat16(r);
}

// ============================================================================
// K0b: gather embeddings and convert to bf16 hi/lo.  n = t*32 + b
// ============================================================================
__global__ void k_convX(const int* __restrict__ sent, const float* __restrict__ embed)
{
    int n = blockIdx.x;
    int t = n >> 5, b = n & 31;
    int word = sent[b * TT + t];
    int k = threadIdx.x;
    float v = embed[(long)word * 256 + k];
    __nv_bfloat16 hi = __float2bfloat16(v);
    float r = v - __bfloat162float(hi);
    g_xhi[n * 256 + k] = hi;
    g_xlo[n * 256 + k] = __float2bfloat16(r);
}

// ============================================================================
// K0c: convert Wout to padded [16][512] bf16 hi/lo (rows 12-15 zero)
// ============================================================================
__global__ void k_convO(const float* __restrict__ Wout)
{
    int tag = blockIdx.x;        // 0..15
    int k = threadIdx.x;         // 0..511
    float v = (tag < NT) ? Wout[tag * 512 + k] : 0.f;
    __nv_bfloat16 hi = __float2bfloat16(v);
    float r = v - __bfloat162float(hi);
    g_Pohi[tag * 512 + k] = hi;
    g_Polo[tag * 512 + k] = __float2bfloat16(r);
}

// ============================================================================
// K1: tensor-core input GEMM via mma.sync bf16 split (R7 design, unchanged).
// ============================================================================
#define ASTR 40
__global__ void __launch_bounds__(256, 2) k_ingemm_mma(
    const float* __restrict__ bf, const float* __restrict__ bb)
{
    __shared__ __align__(16) __nv_bfloat16 sAh[128 * ASTR];
    __shared__ __align__(16) __nv_bfloat16 sAl[128 * ASTR];
    __shared__ __align__(16) __nv_bfloat16 sBh[128 * ASTR];
    __shared__ __align__(16) __nv_bfloat16 sBl[128 * ASTR];

    const int tid = threadIdx.x;
    const int wid = tid >> 5, lane = tid & 31;
    const int m0 = blockIdx.y * 128;
    const int n0 = blockIdx.x * 128;
    const int wm = (wid >> 2) * 64;
    const int wn = (wid & 3) * 32;

    float acc[4][4][4];
#pragma unroll
    for (int i = 0; i < 4; i++)
#pragma unroll
        for (int j = 0; j < 4; j++)
#pragma unroll
            for (int q = 0; q < 4; q++) acc[i][j][q] = 0.f;

    const uint32_t aAh = smem_u32(sAh), aAl = smem_u32(sAl);
    const uint32_t aBh = smem_u32(sBh), aBl = smem_u32(sBl);

    const int arow = lane & 15;
    const int akq  = (lane >> 4) * 16;
    const int brow = (lane & 7) + ((lane >> 4) << 3);
    const int bkq  = ((lane >> 3) & 1) * 16;

    for (int kc = 0; kc < 8; kc++) {
        __syncthreads();
        for (int i = tid; i < 512; i += 256) {
            int r = i >> 2, cq = (i & 3) << 3;
            long srcA = (long)(m0 + r) * 256 + kc * 32 + cq;
            *(int4*)(sAh + r * ASTR + cq) = *(const int4*)(g_Whi + srcA);
            *(int4*)(sAl + r * ASTR + cq) = *(const int4*)(g_Wlo + srcA);
            long srcB = (long)(n0 + r) * 256 + kc * 32 + cq;
            *(int4*)(sBh + r * ASTR + cq) = *(const int4*)(g_xhi + srcB);
            *(int4*)(sBl + r * ASTR + cq) = *(const int4*)(g_xlo + srcB);
        }
        __syncthreads();

#pragma unroll
        for (int ks = 0; ks < 2; ks++) {
            const int akb = ks * 32 + akq;
            const int bkb = ks * 32 + bkq;
            uint32_t Ah[4][4], Bh[4][2], Bl[4][2];
#pragma unroll
            for (int mf = 0; mf < 4; mf++) {
                uint32_t ad = aAh + (uint32_t)((wm + mf * 16 + arow) * (ASTR * 2)) + akb;
                ldsm4(Ah[mf][0], Ah[mf][1], Ah[mf][2], Ah[mf][3], ad);
            }
#pragma unroll
            for (int nf2 = 0; nf2 < 2; nf2++) {
                uint32_t bo = (uint32_t)((wn + nf2 * 16 + brow) * (ASTR * 2)) + bkb;
                uint32_t r0, r1, r2, r3;
                ldsm4(r0, r1, r2, r3, aBh + bo);
                Bh[nf2 * 2][0] = r0; Bh[nf2 * 2][1] = r1;
                Bh[nf2 * 2 + 1][0] = r2; Bh[nf2 * 2 + 1][1] = r3;
                ldsm4(r0, r1, r2, r3, aBl + bo);
                Bl[nf2 * 2][0] = r0; Bl[nf2 * 2][1] = r1;
                Bl[nf2 * 2 + 1][0] = r2; Bl[nf2 * 2 + 1][1] = r3;
            }
#pragma unroll
            for (int mf = 0; mf < 4; mf++)
#pragma unroll
                for (int nf = 0; nf < 4; nf++) {
                    mma16816(acc[mf][nf], Ah[mf], Bh[nf]);
                    mma16816(acc[mf][nf], Ah[mf], Bl[nf]);
                }
#pragma unroll
            for (int mf = 0; mf < 4; mf++) {
                uint32_t Al[4];
                uint32_t ad = aAl + (uint32_t)((wm + mf * 16 + arow) * (ASTR * 2)) + akb;
                ldsm4(Al[0], Al[1], Al[2], Al[3], ad);
#pragma unroll
                for (int nf = 0; nf < 4; nf++)
                    mma16816(acc[mf][nf], Al, Bh[nf]);
            }
        }
    }

#pragma unroll
    for (int mf = 0; mf < 4; mf++) {
        int m = m0 + wm + mf * 16 + (lane >> 2);
        int dirA = m >> 10, gA = m & 1023;
        int mB = m + 8;
        int gB = mB & 1023;
        float biasA = dirA ? bb[gA] : bf[gA];
        float biasB = (mB >> 10) ? bb[gB] : bf[gB];
#pragma unroll
        for (int nf = 0; nf < 4; nf++) {
            int n = n0 + wn + nf * 8 + 2 * (lane & 3);
            int t = n >> 5, b = n & 31;
            float* zpA = g_zpre + ((long)dirA * TT + t) * (G4 * BB) + (long)gA * BB + b;
            *(float2*)zpA = make_float2(acc[mf][nf][0] + biasA, acc[mf][nf][1] + biasA);
            float* zpB = g_zpre + ((long)(mB >> 10) * TT + t) * (G4 * BB) + (long)gB * BB + b;
            *(float2*)zpB = make_float2(acc[mf][nf][2] + biasB, acc[mf][nf][3] + biasB);
        }
    }
}

// ============================================================================
// K1b: initialize h slots + zero barriers.  grid 16 (dir = bid&1, chunk = bid>>1)
// ============================================================================
__global__ void k_inith(const float* __restrict__ h0)
{
    int dir = blockIdx.x & 1;
    int chunk = blockIdx.x >> 1;     // 0..7
    int tid = threadIdx.x;
    int slot = (dir == 0) ? 0 : TT;
    __nv_bfloat16* hbf = (__nv_bfloat16*)(g_hsbf[dir]);
#pragma unroll
    for (int it = 0; it < 4; it++) {
        int s = chunk * 1024 + it * 256 + tid;     // 0..8191
        int k = s >> 5, b = s & 31;
        float v = h0[dir * (BB * HHD) + b * HHD + k];
        g_hs[dir][slot * (HHD * BB) + (k >> 1) * 64 + b * 2 + (k & 1)] = v;
        __nv_bfloat16 hi = __float2bfloat16(v);
        float rem = v - __bfloat162float(hi);
        uint32_t wi = slot * 8192 + (k >> 1) * 64 + b * 2;
        hbf[wi * 2 + (k & 1)] = hi;
        hbf[(wi + 1) * 2 + (k & 1)] = __float2bfloat16(rem);
    }
    if (blockIdx.x == 0) {
        for (int i = tid; i < 2 * TT * BARSTR; i += 256) g_bar[i] = 0;
    }
}

// ============================================================================
// K2: persistent bi-directional LSTM, tensor-core compute, 32 CTAs/dir.
// 64 CTAs x 768 threads: dir = bid>>5, unit group u0 = (bid&31)*8 (32 rows).
// Warps 0-15 (compute): rh = w&1 (16 rows), kc = w>>1 (32 k, 2 kfrags).
//   W_hh frags preloaded in regs; per step 16 LDG.64 h frags + 24 MMAs.
// Warps 16-23 (gates): jj = w-16 (unit), reduce 8 partials x 4 gates,
//   gate math, h stores; single release per CTA after gate bar (target 32).
// ============================================================================
#define ZRED(par,kc,r,bb_) lsm[((((par)*8+(kc))*32+(r))*34) + (bb_)]
#define LSTM_SMEM (2*8*32*34*4 + 8*32*4)

__global__ void __launch_bounds__(768, 1) k_lstm(const float* __restrict__ c0)
{
    extern __shared__ float lsm[];
    float* csm = lsm + 2 * 8 * 32 * 34;     // [8][32]

    const int tid = threadIdx.x;
    const int w = tid >> 5, lane = tid & 31;
    const int dir = blockIdx.x >> 5;
    const int u0 = (blockIdx.x & 31) * 8;
    const int b  = lane;

    if (w >= 16) {
        int jj = w - 16;
        csm[jj * 32 + b] = c0[dir * (BB * HHD) + b * HHD + u0 + jj];
    }
    __syncthreads();

    float* hsBase = g_hs[dir];
    uint32_t* hbfBase = g_hsbf[dir];
    int* bar = g_bar + dir * TT * BARSTR;
    const long zdirbase = (long)dir * (TT * G4 * BB);

    if (w < 16) {
        // ==================== compute warps ====================
        const int tq = lane & 3, tb = lane >> 2;
        const int rh = w & 1, kc = w >> 1;
        const int r1 = rh * 16 + tb, r2 = r1 + 8;
        const int grow1 = (r1 >> 3) * 256 + u0 + (r1 & 7);
        const int grow2 = (r2 >> 3) * 256 + u0 + (r2 & 7);

        uint32_t Ah[2][4], Al[2][4];
        {
            const __nv_bfloat16* WhiB = g_Hhi + (long)dir * 1024 * 256;
            const __nv_bfloat16* WloB = g_Hlo + (long)dir * 1024 * 256;
#pragma unroll
            for (int kf = 0; kf < 2; kf++) {
                int k0 = kc * 32 + kf * 16 + tq * 2;
                Ah[kf][0] = *(const uint32_t*)(WhiB + grow1 * 256 + k0);
                Ah[kf][1] = *(const uint32_t*)(WhiB + grow2 * 256 + k0);
                Ah[kf][2] = *(const uint32_t*)(WhiB + grow1 * 256 + k0 + 8);
                Ah[kf][3] = *(const uint32_t*)(WhiB + grow2 * 256 + k0 + 8);
                Al[kf][0] = *(const uint32_t*)(WloB + grow1 * 256 + k0);
                Al[kf][1] = *(const uint32_t*)(WloB + grow2 * 256 + k0);
                Al[kf][2] = *(const uint32_t*)(WloB + grow1 * 256 + k0 + 8);
                Al[kf][3] = *(const uint32_t*)(WloB + grow2 * 256 + k0 + 8);
            }
        }

        for (int s = 0; s < TT; s++) {
            const int t = (dir == 0) ? s : (TT - 1 - s);
            const int rslot = (dir == 0) ? s : (t + 1);
            const int par = s & 1;

            if (s > 0) {
                if (tid == 0) {
                    while (ldacq(&bar[(s - 1) * BARSTR]) < 32) pause_short();
                }
            }
            asm volatile("bar.sync 1, 512;" ::: "memory");

            const uint32_t* hb = hbfBase + (uint32_t)rslot * 8192;
            float C[4][4];
#pragma unroll
            for (int nf = 0; nf < 4; nf++)
#pragma unroll
                for (int q = 0; q < 4; q++) C[nf][q] = 0.f;

#pragma unroll
            for (int kf = 0; kf < 2; kf++) {
                int qa = kc * 16 + kf * 8 + tq;
                ull Bw[4][2];
#pragma unroll
                for (int nf = 0; nf < 4; nf++) {
                    int bcol = (tb + nf * 8) * 2;
                    Bw[nf][0] = *(const ull*)(hb + qa * 64 + bcol);
                    Bw[nf][1] = *(const ull*)(hb + (qa + 4) * 64 + bcol);
                }
#pragma unroll
                for (int nf = 0; nf < 4; nf++) {
                    uint32_t bh[2], bl[2];
                    bh[0] = (uint32_t)(Bw[nf][0]);
                    bl[0] = (uint32_t)(Bw[nf][0] >> 32);
                    bh[1] = (uint32_t)(Bw[nf][1]);
                    bl[1] = (uint32_t)(Bw[nf][1] >> 32);
                    mma16816(C[nf], Ah[kf], bh);
                    mma16816(C[nf], Al[kf], bh);
                    mma16816(C[nf], Ah[kf], bl);
                }
            }

#pragma unroll
            for (int nf = 0; nf < 4; nf++) {
                int col = nf * 8 + tq * 2;
                *(float2*)&ZRED(par, kc, r1, col) = make_float2(C[nf][0], C[nf][1]);
                *(float2*)&ZRED(par, kc, r2, col) = make_float2(C[nf][2], C[nf][3]);
            }
            asm volatile("bar.arrive 2, 768;" ::: "memory");
        }
    } else {
        // ==================== gate warps ====================
        const int jj = w - 16;     // 0..7
        __nv_bfloat16* hbf16 = (__nv_bfloat16*)hbfBase;
        for (int s = 0; s < TT; s++) {
            const int t = (dir == 0) ? s : (TT - 1 - s);
            const int wslot = (dir == 0) ? (s + 1) : t;
            const int par = s & 1;

            const float* zb = g_zpre + zdirbase + (long)t * (G4 * BB) + (u0 + jj) * BB + b;
            float zp0 = zb[0 * HHD * BB];
            float zp1 = zb[1 * HHD * BB];
            float zp2 = zb[2 * HHD * BB];
            float zp3 = zb[3 * HHD * BB];

            asm volatile("bar.sync 2, 768;" ::: "memory");

            float zi = zp0, zf = zp1, zg = zp2, zo = zp3;
#pragma unroll
            for (int c = 0; c < 8; c++) {
                zi += ZRED(par, c, jj, b);
                zf += ZRED(par, c, 8 + jj, b);
                zg += ZRED(par, c, 16 + jj, b);
                zo += ZRED(par, c, 24 + jj, b);
            }
            float cc = sigf(zf) * csm[jj * 32 + b] + sigf(zi) * tanhfast(zg);
            csm[jj * 32 + b] = cc;
            float h = sigf(zo) * tanhfast(cc);
            int j = u0 + jj;
            hsBase[wslot * (HHD * BB) + (j >> 1) * 64 + b * 2 + (j & 1)] = h;
            __nv_bfloat16 hh = __float2bfloat16(h);
            float hrem = h - __bfloat162float(hh);
            uint32_t wi = (uint32_t)wslot * 8192 + (uint32_t)(j >> 1) * 64 + b * 2;
            hbf16[wi * 2 + (j & 1)] = hh;
            hbf16[(wi + 1) * 2 + (j & 1)] = __float2bfloat16(hrem);

            asm volatile("bar.sync 3, 256;" ::: "memory");
            if (w == 16 && lane == 0) redrel(&bar[s * BARSTR]);
        }
    }
}

// ============================================================================
// K3: output projection via HMMA on the bf16 h fragments.
// CTA per t, 256 thr (8 warps): warps 0-3 fwd kfrags [4w,4w+4), 4-7 bwd.
// C = Wout_hi*h_hi + Wout_lo*h_hi + Wout_hi*h_lo, fp32 accum, SMEM reduce.
// ============================================================================
__global__ void __launch_bounds__(256) k_projmma(const float* __restrict__ bout)
{
    __shared__ float zp[8][16][33];
    const int t = blockIdx.x;
    const int tid = threadIdx.x;
    const int w = tid >> 5, lane = tid & 31;
    const int tq = lane & 3, tb = lane >> 2;
    const int d = w >> 2;                       // 0 fwd, 1 bwd
    const int kfbase = (w & 3) * 4;
    const int slot = (d == 0) ? (t + 1) : t;
    const uint32_t* hb = g_hsbf[d] + (uint32_t)slot * 8192;

    float C[4][4];
#pragma unroll
    for (int nf = 0; nf < 4; nf++)
#pragma unroll
        for (int q = 0; q < 4; q++) C[nf][q] = 0.f;

#pragma unroll
    for (int kf = 0; kf < 4; kf++) {
        int col = d * 256 + (kfbase + kf) * 16 + tq * 2;
        uint32_t ah[4], al[4];
        ah[0] = *(const uint32_t*)(g_Pohi + tb * 512 + col);
        ah[1] = *(const uint32_t*)(g_Pohi + (tb + 8) * 512 + col);
        ah[2] = *(const uint32_t*)(g_Pohi + tb * 512 + col + 8);
        ah[3] = *(const uint32_t*)(g_Pohi + (tb + 8) * 512 + col + 8);
        al[0] = *(const uint32_t*)(g_Polo + tb * 512 + col);
        al[1] = *(const uint32_t*)(g_Polo + (tb + 8) * 512 + col);
        al[2] = *(const uint32_t*)(g_Polo + tb * 512 + col + 8);
        al[3] = *(const uint32_t*)(g_Polo + (tb + 8) * 512 + col + 8);

        int qa = (kfbase + kf) * 8 + tq;
#pragma unroll
        for (int nf = 0; nf < 4; nf++) {
            int bcol = (tb + nf * 8) * 2;
            ull w0 = *(const ull*)(hb + qa * 64 + bcol);
            ull w1 = *(const ull*)(hb + (qa + 4) * 64 + bcol);
            uint32_t bh[2], bl[2];
            bh[0] = (uint32_t)w0; bl[0] = (uint32_t)(w0 >> 32);
            bh[1] = (uint32_t)w1; bl[1] = (uint32_t)(w1 >> 32);
            mma16816(C[nf], ah, bh);
            mma16816(C[nf], al, bh);
            mma16816(C[nf], ah, bl);
        }
    }

#pragma unroll
    for (int nf = 0; nf < 4; nf++) {
        int col = nf * 8 + tq * 2;
        zp[w][tb][col] = C[nf][0];     zp[w][tb][col + 1] = C[nf][1];
        zp[w][tb + 8][col] = C[nf][2]; zp[w][tb + 8][col + 1] = C[nf][3];
    }
    __syncthreads();

    for (int i = tid; i < NT * 32; i += 256) {
        int tag = i >> 5, b = i & 31;
        float s = bout[tag];
#pragma unroll
        for (int ww = 0; ww < 8; ww++) s += zp[ww][tag][b];
        g_feats[(b * TT + t) * NT + tag] = s;
    }
}

// ============================================================================
// K4: Viterbi decode (one warp per batch element) + backtrace.
// ============================================================================
__global__ void __launch_bounds__(32) k_viterbi(
    const float* __restrict__ trans, float* __restrict__ out)
{
    __shared__ float tsm[NT * NT];
    __shared__ float fv[NT];
    __shared__ signed char bp[TT][NT];
    __shared__ float fsm[TT * NT];

    const int b = blockIdx.x;
    const int tid = threadIdx.x;

    const float* fb = g_feats + (long)b * TT * NT;
    for (int i = tid; i < TT * NT; i += 32) fsm[i] = fb[i];
    for (int i = tid; i < NT * NT; i += 32) tsm[i] = trans[i];
    if (tid < NT) fv[tid] = (tid == START_IDX) ? 0.0f : -10000.0f;
    __syncwarp();

    for (int t = 0; t < TT; t++) {
        float bestv = -1e30f; int bestp = 0;
        if (tid < NT) {
            bestv = fv[0] + tsm[tid * NT + 0]; bestp = 0;
#pragma unroll
            for (int p = 1; p < NT; p++) {
                float v = fv[p] + tsm[tid * NT + p];
                if (v > bestv) { bestv = v; bestp = p; }
            }
        }
        __syncwarp();
        if (tid < NT) {
            fv[tid] = bestv + fsm[t * NT + tid];
            bp[t][tid] = (signed char)bestp;
        }
        __syncwarp();
    }

    if (tid == 0) {
        float best = fv[0] + tsm[STOP_IDX * NT + 0]; int bt = 0;
#pragma unroll
        for (int n = 1; n < NT; n++) {
            float v = fv[n] + tsm[STOP_IDX * NT + n];
            if (v > best) { best = v; bt = n; }
        }
        out[b] = best;
        int tag = bt;
        for (int t = TT - 1; t >= 0; t--) {
            out[32 + b * TT + t] = (float)tag;
            tag = bp[t][tag];
        }
    }
}

// ============================================================================
extern "C" void kernel_launch(void* const* d_in, const int* in_sizes, int n_in,
                              void* d_out, int out_size)
{
    const int*   sent  = (const int*)  d_in[0];
    const float* embed = (const float*)d_in[1];
    const float* Wihf  = (const float*)d_in[2];
    const float* Whhf  = (const float*)d_in[3];
    const float* bf    = (const float*)d_in[4];
    const float* Wihb  = (const float*)d_in[5];
    const float* Whhb  = (const float*)d_in[6];
    const float* bb    = (const float*)d_in[7];
    const float* Wout  = (const float*)d_in[8];
    const float* bout  = (const float*)d_in[9];
    const float* trans = (const float*)d_in[10];
    const float* h0    = (const float*)d_in[11];
    const float* c0    = (const float*)d_in[12];
    float* out = (float*)d_out;

    cudaFuncSetAttribute(k_lstm, cudaFuncAttributeMaxDynamicSharedMemorySize, LSTM_SMEM);

    k_convW2<<<4096, 256>>>(Wihf, Wihb, Whhf, Whhb);
    k_convX<<<8192, 256>>>(sent, embed);
    k_convO<<<16, 512>>>(Wout);
    k_inith<<<16, 256>>>(h0);
    k_ingemm_mma<<<dim3(64, 16), 256>>>(bf, bb);
    k_lstm<<<64, 768, LSTM_SMEM>>>(c0);
    k_projmma<<<TT, 256>>>(bout);
    k_viterbi<<<BB, 32>>>(trans, out);
}

// round 13
// speedup vs baseline: 1.3547x; 1.3547x over previous
#include <cuda_runtime.h>
#include <cuda_bf16.h>
#include <cstdint>

// Problem constants
#define TT   256     // sequence length
#define BB   32      // batch
#define EMB  256
#define HHD  256     // per-direction hidden
#define G4   1024    // 4*HHD
#define NT   12
#define START_IDX 10
#define STOP_IDX  11
#define BARSTR 32    // barrier slot stride in ints (128B line padding)

typedef unsigned long long ull;

// ---------------- scratch (device globals; no allocation allowed) ----------
__device__ __align__(16) float g_zpre[2L * TT * G4 * BB];   // [dir][t][gate_row][b]
// bf16 split h (fragment layout): word wi = slot*8192 + (k>>1)*64 + b*2
//   word wi = {hi(h[2q]), hi(h[2q+1])}, word wi+1 = {lo(h[2q]), lo(h[2q+1])}
__device__ __align__(16) uint32_t g_hsbf[2][(TT + 1) * 8192];
__device__ __align__(16) float g_feats[BB * TT * NT];       // [b][t][tag]
__device__ int   g_bar[2 * TT * BARSTR];                    // padded step counters (target 64)
// bf16 split operands
__device__ __align__(16) __nv_bfloat16 g_Whi[2048 * 256];   // W_ih rows m = dir*1024 + row
__device__ __align__(16) __nv_bfloat16 g_Wlo[2048 * 256];
__device__ __align__(16) __nv_bfloat16 g_Hhi[2048 * 256];   // W_hh rows
__device__ __align__(16) __nv_bfloat16 g_Hlo[2048 * 256];
__device__ __align__(16) __nv_bfloat16 g_xhi[8192 * 256];   // x rows n = t*32 + b
__device__ __align__(16) __nv_bfloat16 g_xlo[8192 * 256];
__device__ __align__(16) __nv_bfloat16 g_Pohi[16 * 512];    // Wout padded (rows 12-15 zero)
__device__ __align__(16) __nv_bfloat16 g_Polo[16 * 512];

// ---------------- generic helpers ------------------------------------------
__device__ __forceinline__ int ldacq(const int* p) {
    int v; asm volatile("ld.acquire.gpu.global.s32 %0, [%1];" : "=r"(v) : "l"(p)); return v;
}
__device__ __forceinline__ void redrel(int* p) {
    asm volatile("red.release.gpu.global.add.s32 [%0], 1;" :: "l"(p));
}
__device__ __forceinline__ void pause_short() {
    uint32_t x = 0;
#pragma unroll
    for (int i = 0; i < 12; i++) asm volatile("add.u32 %0, %0, 1;" : "+r"(x));
}
__device__ __forceinline__ float sigf(float x) {
    float e = __expf(-x);
    return __fdividef(1.0f, 1.0f + e);
}
__device__ __forceinline__ float tanhfast(float x) {
    float ax = fminf(fabsf(x), 15.0f);
    float e = __expf(2.0f * ax);
    float t = __fdividef(e - 1.0f, e + 1.0f);
    return copysignf(t, x);
}
__device__ __forceinline__ uint32_t smem_u32(const void* p) {
    uint32_t a;
    asm("{ .reg .u64 t; cvta.to.shared.u64 t, %1; cvt.u32.u64 %0, t; }" : "=r"(a) : "l"(p));
    return a;
}
__device__ __forceinline__ void ldsm4(uint32_t& r0, uint32_t& r1, uint32_t& r2, uint32_t& r3,
                                      uint32_t addr) {
    asm volatile("ldmatrix.sync.aligned.m8n8.x4.shared.b16 {%0,%1,%2,%3}, [%4];"
                 : "=r"(r0), "=r"(r1), "=r"(r2), "=r"(r3) : "r"(addr));
}
__device__ __forceinline__ void mma16816(float* c, const uint32_t* a, const uint32_t* b) {
    asm volatile("mma.sync.aligned.m16n8k16.row.col.f32.bf16.bf16.f32 "
                 "{%0,%1,%2,%3}, {%4,%5,%6,%7}, {%8,%9}, {%0,%1,%2,%3};"
                 : "+f"(c[0]), "+f"(c[1]), "+f"(c[2]), "+f"(c[3])
                 : "r"(a[0]), "r"(a[1]), "r"(a[2]), "r"(a[3]), "r"(b[0]), "r"(b[1]));
}

// ============================================================================
// K0a: convert W_ih AND W_hh (both dirs) to bf16 hi/lo.  grid 4096.
// ============================================================================
__global__ void k_convW2(const float* __restrict__ Wihf, const float* __restrict__ Wihb,
                         const float* __restrict__ Whhf, const float* __restrict__ Whhb)
{
    int m = blockIdx.x;          // 0..4095
    int k = threadIdx.x;         // 0..255
    const float* src;
    __nv_bfloat16 *dh, *dl;
    int mm;
    if (m < 2048) {
        src = (m < 1024) ? Wihf : Wihb; mm = m;
        dh = g_Whi; dl = g_Wlo;
    } else {
        int m2 = m - 2048;
        src = (m2 < 1024) ? Whhf : Whhb; mm = m2;
        dh = g_Hhi; dl = g_Hlo;
    }
    float v = src[(mm & 1023) * 256 + k];
    __nv_bfloat16 hi = __float2bfloat16(v);
    float r = v - __bfloat162float(hi);
    dh[mm * 256 + k] = hi;
    dl[mm * 256 + k] = __float2bfloat16(r);
}

// ============================================================================
// K0b: gather embeddings and convert to bf16 hi/lo.  n = t*32 + b
// ============================================================================
__global__ void k_convX(const int* __restrict__ sent, const float* __restrict__ embed)
{
    int n = blockIdx.x;
    int t = n >> 5, b = n & 31;
    int word = sent[b * TT + t];
    int k = threadIdx.x;
    float v = embed[(long)word * 256 + k];
    __nv_bfloat16 hi = __float2bfloat16(v);
    float r = v - __bfloat162float(hi);
    g_xhi[n * 256 + k] = hi;
    g_xlo[n * 256 + k] = __float2bfloat16(r);
}

// ============================================================================
// K0c: convert Wout to padded [16][512] bf16 hi/lo (rows 12-15 zero)
// ============================================================================
__global__ void k_convO(const float* __restrict__ Wout)
{
    int tag = blockIdx.x;        // 0..15
    int k = threadIdx.x;         // 0..511
    float v = (tag < NT) ? Wout[tag * 512 + k] : 0.f;
    __nv_bfloat16 hi = __float2bfloat16(v);
    float r = v - __bfloat162float(hi);
    g_Pohi[tag * 512 + k] = hi;
    g_Polo[tag * 512 + k] = __float2bfloat16(r);
}

// ============================================================================
// K1: tensor-core input GEMM via mma.sync bf16 split (R7 design, unchanged).
// ============================================================================
#define ASTR 40
__global__ void __launch_bounds__(256, 2) k_ingemm_mma(
    const float* __restrict__ bf, const float* __restrict__ bb)
{
    __shared__ __align__(16) __nv_bfloat16 sAh[128 * ASTR];
    __shared__ __align__(16) __nv_bfloat16 sAl[128 * ASTR];
    __shared__ __align__(16) __nv_bfloat16 sBh[128 * ASTR];
    __shared__ __align__(16) __nv_bfloat16 sBl[128 * ASTR];

    const int tid = threadIdx.x;
    const int wid = tid >> 5, lane = tid & 31;
    const int m0 = blockIdx.y * 128;
    const int n0 = blockIdx.x * 128;
    const int wm = (wid >> 2) * 64;
    const int wn = (wid & 3) * 32;

    float acc[4][4][4];
#pragma unroll
    for (int i = 0; i < 4; i++)
#pragma unroll
        for (int j = 0; j < 4; j++)
#pragma unroll
            for (int q = 0; q < 4; q++) acc[i][j][q] = 0.f;

    const uint32_t aAh = smem_u32(sAh), aAl = smem_u32(sAl);
    const uint32_t aBh = smem_u32(sBh), aBl = smem_u32(sBl);

    const int arow = lane & 15;
    const int akq  = (lane >> 4) * 16;
    const int brow = (lane & 7) + ((lane >> 4) << 3);
    const int bkq  = ((lane >> 3) & 1) * 16;

    for (int kc = 0; kc < 8; kc++) {
        __syncthreads();
        for (int i = tid; i < 512; i += 256) {
            int r = i >> 2, cq = (i & 3) << 3;
            long srcA = (long)(m0 + r) * 256 + kc * 32 + cq;
            *(int4*)(sAh + r * ASTR + cq) = *(const int4*)(g_Whi + srcA);
            *(int4*)(sAl + r * ASTR + cq) = *(const int4*)(g_Wlo + srcA);
            long srcB = (long)(n0 + r) * 256 + kc * 32 + cq;
            *(int4*)(sBh + r * ASTR + cq) = *(const int4*)(g_xhi + srcB);
            *(int4*)(sBl + r * ASTR + cq) = *(const int4*)(g_xlo + srcB);
        }
        __syncthreads();

#pragma unroll
        for (int ks = 0; ks < 2; ks++) {
            const int akb = ks * 32 + akq;
            const int bkb = ks * 32 + bkq;
            uint32_t Ah[4][4], Bh[4][2], Bl[4][2];
#pragma unroll
            for (int mf = 0; mf < 4; mf++) {
                uint32_t ad = aAh + (uint32_t)((wm + mf * 16 + arow) * (ASTR * 2)) + akb;
                ldsm4(Ah[mf][0], Ah[mf][1], Ah[mf][2], Ah[mf][3], ad);
            }
#pragma unroll
            for (int nf2 = 0; nf2 < 2; nf2++) {
                uint32_t bo = (uint32_t)((wn + nf2 * 16 + brow) * (ASTR * 2)) + bkb;
                uint32_t r0, r1, r2, r3;
                ldsm4(r0, r1, r2, r3, aBh + bo);
                Bh[nf2 * 2][0] = r0; Bh[nf2 * 2][1] = r1;
                Bh[nf2 * 2 + 1][0] = r2; Bh[nf2 * 2 + 1][1] = r3;
                ldsm4(r0, r1, r2, r3, aBl + bo);
                Bl[nf2 * 2][0] = r0; Bl[nf2 * 2][1] = r1;
                Bl[nf2 * 2 + 1][0] = r2; Bl[nf2 * 2 + 1][1] = r3;
            }
#pragma unroll
            for (int mf = 0; mf < 4; mf++)
#pragma unroll
                for (int nf = 0; nf < 4; nf++) {
                    mma16816(acc[mf][nf], Ah[mf], Bh[nf]);
                    mma16816(acc[mf][nf], Ah[mf], Bl[nf]);
                }
#pragma unroll
            for (int mf = 0; mf < 4; mf++) {
                uint32_t Al[4];
                uint32_t ad = aAl + (uint32_t)((wm + mf * 16 + arow) * (ASTR * 2)) + akb;
                ldsm4(Al[0], Al[1], Al[2], Al[3], ad);
#pragma unroll
                for (int nf = 0; nf < 4; nf++)
                    mma16816(acc[mf][nf], Al, Bh[nf]);
            }
        }
    }

#pragma unroll
    for (int mf = 0; mf < 4; mf++) {
        int m = m0 + wm + mf * 16 + (lane >> 2);
        int dirA = m >> 10, gA = m & 1023;
        int mB = m + 8;
        int gB = mB & 1023;
        float biasA = dirA ? bb[gA] : bf[gA];
        float biasB = (mB >> 10) ? bb[gB] : bf[gB];
#pragma unroll
        for (int nf = 0; nf < 4; nf++) {
            int n = n0 + wn + nf * 8 + 2 * (lane & 3);
            int t = n >> 5, b = n & 31;
            float* zpA = g_zpre + ((long)dirA * TT + t) * (G4 * BB) + (long)gA * BB + b;
            *(float2*)zpA = make_float2(acc[mf][nf][0] + biasA, acc[mf][nf][1] + biasA);
            float* zpB = g_zpre + ((long)(mB >> 10) * TT + t) * (G4 * BB) + (long)gB * BB + b;
            *(float2*)zpB = make_float2(acc[mf][nf][2] + biasB, acc[mf][nf][3] + biasB);
        }
    }
}

// ============================================================================
// K1b: initialize bf16 h slots + zero barriers.  grid 16.
// ============================================================================
__global__ void k_inith(const float* __restrict__ h0)
{
    int dir = blockIdx.x & 1;
    int chunk = blockIdx.x >> 1;     // 0..7
    int tid = threadIdx.x;
    int slot = (dir == 0) ? 0 : TT;
    __nv_bfloat16* hbf = (__nv_bfloat16*)(g_hsbf[dir]);
#pragma unroll
    for (int it = 0; it < 4; it++) {
        int s = chunk * 1024 + it * 256 + tid;     // 0..8191
        int k = s >> 5, b = s & 31;
        float v = h0[dir * (BB * HHD) + b * HHD + k];
        __nv_bfloat16 hi = __float2bfloat16(v);
        float rem = v - __bfloat162float(hi);
        uint32_t wi = slot * 8192 + (k >> 1) * 64 + b * 2;
        hbf[wi * 2 + (k & 1)] = hi;
        hbf[(wi + 1) * 2 + (k & 1)] = __float2bfloat16(rem);
    }
    if (blockIdx.x == 0) {
        for (int i = tid; i < 2 * TT * BARSTR; i += 256) g_bar[i] = 0;
    }
}

// ============================================================================
// K2: persistent bi-directional LSTM, tensor-core compute (R11 shape).
// 128 CTAs x 384 threads: dir = bid>>6, unit group j0 = (bid&63)*4 (16 rows).
// Warps 0-7 (compute): warp w owns kfrags {2w, 2w+1}; W_hh frags in regs.
//   Per step: 16 LDG.64 h frags, 24 MMAs, STS partials, bar.arrive 2.
// Warps 8-11 (gates): prefetch z_pre, bar.sync 2, reduce, gates, bf16 h
//   stores; gate-only bar.sync 3,128 then ONE release per CTA (target 64).
// ============================================================================
__global__ void __launch_bounds__(384, 1) k_lstm(const float* __restrict__ c0)
{
    __shared__ float zred[2][8][16][34];   // parity x warp x row x batch(pad 34)
    __shared__ float csm[4][32];

    const int tid = threadIdx.x;
    const int w = tid >> 5, lane = tid & 31;
    const int dir = blockIdx.x >> 6;
    const int j0 = (blockIdx.x & 63) * 4;
    const int b  = lane;

    if (w >= 8) {
        int jj = w - 8;
        csm[jj][b] = c0[dir * (BB * HHD) + b * HHD + j0 + jj];
    }
    __syncthreads();

    uint32_t* hbfBase = g_hsbf[dir];
    int* bar = g_bar + dir * TT * BARSTR;
    const long zdirbase = (long)dir * (TT * G4 * BB);

    if (w < 8) {
        // ==================== compute warps ====================
        const int tq = lane & 3, tb = lane >> 2;
        uint32_t Ah[2][4], Al[2][4];
        {
            const __nv_bfloat16* WhiB = g_Hhi + (long)dir * 1024 * 256;
            const __nv_bfloat16* WloB = g_Hlo + (long)dir * 1024 * 256;
            int rr = tb;           // frag rows rr, rr+8
            int grow1 = (rr >> 2) * 256 + j0 + (rr & 3);
            int rr8 = rr + 8;
            int grow2 = (rr8 >> 2) * 256 + j0 + (rr8 & 3);
#pragma unroll
            for (int kf = 0; kf < 2; kf++) {
                int k0 = (2 * w + kf) * 16 + tq * 2;
                Ah[kf][0] = *(const uint32_t*)(WhiB + grow1 * 256 + k0);
                Ah[kf][1] = *(const uint32_t*)(WhiB + grow2 * 256 + k0);
                Ah[kf][2] = *(const uint32_t*)(WhiB + grow1 * 256 + k0 + 8);
                Ah[kf][3] = *(const uint32_t*)(WhiB + grow2 * 256 + k0 + 8);
                Al[kf][0] = *(const uint32_t*)(WloB + grow1 * 256 + k0);
                Al[kf][1] = *(const uint32_t*)(WloB + grow2 * 256 + k0);
                Al[kf][2] = *(const uint32_t*)(WloB + grow1 * 256 + k0 + 8);
                Al[kf][3] = *(const uint32_t*)(WloB + grow2 * 256 + k0 + 8);
            }
        }
        const int rr = tb;
        const int q0 = w * 16 + tq;

        for (int s = 0; s < TT; s++) {
            const int t = (dir == 0) ? s : (TT - 1 - s);
            const int rslot = (dir == 0) ? s : (t + 1);
            const int par = s & 1;

            if (s > 0) {
                if (tid == 0) {
                    while (ldacq(&bar[(s - 1) * BARSTR]) < 64) pause_short();
                }
            }
            asm volatile("bar.sync 1, 256;" ::: "memory");

            const uint32_t* hb = hbfBase + (uint32_t)rslot * 8192;
            ull Bw[2][4][2];
#pragma unroll
            for (int kf = 0; kf < 2; kf++) {
                int qa = q0 + kf * 8;
#pragma unroll
                for (int nf = 0; nf < 4; nf++) {
                    int bcol = (tb + nf * 8) * 2;
                    Bw[kf][nf][0] = *(const ull*)(hb + (qa) * 64 + bcol);
                    Bw[kf][nf][1] = *(const ull*)(hb + (qa + 4) * 64 + bcol);
                }
            }

            float C[4][4];
#pragma unroll
            for (int nf = 0; nf < 4; nf++)
#pragma unroll
                for (int q = 0; q < 4; q++) C[nf][q] = 0.f;
#pragma unroll
            for (int kf = 0; kf < 2; kf++) {
#pragma unroll
                for (int nf = 0; nf < 4; nf++) {
                    uint32_t bh[2], bl[2];
                    bh[0] = (uint32_t)(Bw[kf][nf][0]);
                    bl[0] = (uint32_t)(Bw[kf][nf][0] >> 32);
                    bh[1] = (uint32_t)(Bw[kf][nf][1]);
                    bl[1] = (uint32_t)(Bw[kf][nf][1] >> 32);
                    mma16816(C[nf], Ah[kf], bh);
                    mma16816(C[nf], Al[kf], bh);
                    mma16816(C[nf], Ah[kf], bl);
                }
            }

#pragma unroll
            for (int nf = 0; nf < 4; nf++) {
                int col = nf * 8 + tq * 2;
                *(float2*)&zred[par][w][rr][col]     = make_float2(C[nf][0], C[nf][1]);
                *(float2*)&zred[par][w][rr + 8][col] = make_float2(C[nf][2], C[nf][3]);
            }
            asm volatile("bar.arrive 2, 384;" ::: "memory");
        }
    } else {
        // ==================== gate warps ====================
        const int jj = w - 8;
        __nv_bfloat16* hbf16 = (__nv_bfloat16*)hbfBase;
        for (int s = 0; s < TT; s++) {
            const int t = (dir == 0) ? s : (TT - 1 - s);
            const int wslot = (dir == 0) ? (s + 1) : t;
            const int par = s & 1;

            const float* zb = g_zpre + zdirbase + (long)t * (G4 * BB) + (j0 + jj) * BB + b;
            float zp0 = zb[0 * HHD * BB];
            float zp1 = zb[1 * HHD * BB];
            float zp2 = zb[2 * HHD * BB];
            float zp3 = zb[3 * HHD * BB];

            asm volatile("bar.sync 2, 384;" ::: "memory");

            float zi = zp0, zf = zp1, zg = zp2, zo = zp3;
#pragma unroll
            for (int c = 0; c < 8; c++) {
                zi += zred[par][c][0 * 4 + jj][b];
                zf += zred[par][c][1 * 4 + jj][b];
                zg += zred[par][c][2 * 4 + jj][b];
                zo += zred[par][c][3 * 4 + jj][b];
            }
            float cc = sigf(zf) * csm[jj][b] + sigf(zi) * tanhfast(zg);
            csm[jj][b] = cc;
            float h = sigf(zo) * tanhfast(cc);
            int j = j0 + jj;
            __nv_bfloat16 hh = __float2bfloat16(h);
            float hrem = h - __bfloat162float(hh);
            uint32_t wi = (uint32_t)wslot * 8192 + (uint32_t)(j >> 1) * 64 + b * 2;
            hbf16[wi * 2 + (j & 1)] = hh;
            hbf16[(wi + 1) * 2 + (j & 1)] = __float2bfloat16(hrem);

            asm volatile("bar.sync 3, 128;" ::: "memory");   // gate warps only
            if (w == 8 && lane == 0) redrel(&bar[s * BARSTR]);
        }
    }
}

// ============================================================================
// K3: output projection via HMMA on the bf16 h fragments.
// CTA per t, 256 thr (8 warps): warps 0-3 fwd kfrags [4w,4w+4), 4-7 bwd.
// ============================================================================
__global__ void __launch_bounds__(256) k_projmma(const float* __restrict__ bout)
{
    __shared__ float zp[8][16][33];
    const int t = blockIdx.x;
    const int tid = threadIdx.x;
    const int w = tid >> 5, lane = tid & 31;
    const int tq = lane & 3, tb = lane >> 2;
    const int d = w >> 2;                       // 0 fwd, 1 bwd
    const int kfbase = (w & 3) * 4;
    const int slot = (d == 0) ? (t + 1) : t;
    const uint32_t* hb = g_hsbf[d] + (uint32_t)slot * 8192;

    float C[4][4];
#pragma unroll
    for (int nf = 0; nf < 4; nf++)
#pragma unroll
        for (int q = 0; q < 4; q++) C[nf][q] = 0.f;

#pragma unroll
    for (int kf = 0; kf < 4; kf++) {
        int col = d * 256 + (kfbase + kf) * 16 + tq * 2;
        uint32_t ah[4], al[4];
        ah[0] = *(const uint32_t*)(g_Pohi + tb * 512 + col);
        ah[1] = *(const uint32_t*)(g_Pohi + (tb + 8) * 512 + col);
        ah[2] = *(const uint32_t*)(g_Pohi + tb * 512 + col + 8);
        ah[3] = *(const uint32_t*)(g_Pohi + (tb + 8) * 512 + col + 8);
        al[0] = *(const uint32_t*)(g_Polo + tb * 512 + col);
        al[1] = *(const uint32_t*)(g_Polo + (tb + 8) * 512 + col);
        al[2] = *(const uint32_t*)(g_Polo + tb * 512 + col + 8);
        al[3] = *(const uint32_t*)(g_Polo + (tb + 8) * 512 + col + 8);

        int qa = (kfbase + kf) * 8 + tq;
#pragma unroll
        for (int nf = 0; nf < 4; nf++) {
            int bcol = (tb + nf * 8) * 2;
            ull w0 = *(const ull*)(hb + qa * 64 + bcol);
            ull w1 = *(const ull*)(hb + (qa + 4) * 64 + bcol);
            uint32_t bh[2], bl[2];
            bh[0] = (uint32_t)w0; bl[0] = (uint32_t)(w0 >> 32);
            bh[1] = (uint32_t)w1; bl[1] = (uint32_t)(w1 >> 32);
            mma16816(C[nf], ah, bh);
            mma16816(C[nf], al, bh);
            mma16816(C[nf], ah, bl);
        }
    }

#pragma unroll
    for (int nf = 0; nf < 4; nf++) {
        int col = nf * 8 + tq * 2;
        zp[w][tb][col] = C[nf][0];     zp[w][tb][col + 1] = C[nf][1];
        zp[w][tb + 8][col] = C[nf][2]; zp[w][tb + 8][col + 1] = C[nf][3];
    }
    __syncthreads();

    for (int i = tid; i < NT * 32; i += 256) {
        int tag = i >> 5, b = i & 31;
        float s = bout[tag];
#pragma unroll
        for (int ww = 0; ww < 8; ww++) s += zp[ww][tag][b];
        g_feats[(b * TT + t) * NT + tag] = s;
    }
}

// ============================================================================
// K4: Viterbi decode (one warp per batch element) + backtrace.
// ============================================================================
__global__ void __launch_bounds__(32) k_viterbi(
    const float* __restrict__ trans, float* __restrict__ out)
{
    __shared__ float tsm[NT * NT];
    __shared__ float fv[NT];
    __shared__ signed char bp[TT][NT];
    __shared__ float fsm[TT * NT];

    const int b = blockIdx.x;
    const int tid = threadIdx.x;

    const float* fb = g_feats + (long)b * TT * NT;
    for (int i = tid; i < TT * NT; i += 32) fsm[i] = fb[i];
    for (int i = tid; i < NT * NT; i += 32) tsm[i] = trans[i];
    if (tid < NT) fv[tid] = (tid == START_IDX) ? 0.0f : -10000.0f;
    __syncwarp();

    for (int t = 0; t < TT; t++) {
        float bestv = -1e30f; int bestp = 0;
        if (tid < NT) {
            bestv = fv[0] + tsm[tid * NT + 0]; bestp = 0;
#pragma unroll
            for (int p = 1; p < NT; p++) {
                float v = fv[p] + tsm[tid * NT + p];
                if (v > bestv) { bestv = v; bestp = p; }
            }
        }
        __syncwarp();
        if (tid < NT) {
            fv[tid] = bestv + fsm[t * NT + tid];
            bp[t][tid] = (signed char)bestp;
        }
        __syncwarp();
    }

    if (tid == 0) {
        float best = fv[0] + tsm[STOP_IDX * NT + 0]; int bt = 0;
#pragma unroll
        for (int n = 1; n < NT; n++) {
            float v = fv[n] + tsm[STOP_IDX * NT + n];
            if (v > best) { best = v; bt = n; }
        }
        out[b] = best;
        int tag = bt;
        for (int t = TT - 1; t >= 0; t--) {
            out[32 + b * TT + t] = (float)tag;
            tag = bp[t][tag];
        }
    }
}

// ============================================================================
extern "C" void kernel_launch(void* const* d_in, const int* in_sizes, int n_in,
                              void* d_out, int out_size)
{
    const int*   sent  = (const int*)  d_in[0];
    const float* embed = (const float*)d_in[1];
    const float* Wihf  = (const float*)d_in[2];
    const float* Whhf  = (const float*)d_in[3];
    const float* bf    = (const float*)d_in[4];
    const float* Wihb  = (const float*)d_in[5];
    const float* Whhb  = (const float*)d_in[6];
    const float* bb    = (const float*)d_in[7];
    const float* Wout  = (const float*)d_in[8];
    const float* bout  = (const float*)d_in[9];
    const float* trans = (const float*)d_in[10];
    const float* h0    = (const float*)d_in[11];
    const float* c0    = (const float*)d_in[12];
    float* out = (float*)d_out;

    k_convW2<<<4096, 256>>>(Wihf, Wihb, Whhf, Whhb);
    k_convX<<<8192, 256>>>(sent, embed);
    k_convO<<<16, 512>>>(Wout);
    k_inith<<<16, 256>>>(h0);
    k_ingemm_mma<<<dim3(64, 16), 256>>>(bf, bb);
    k_lstm<<<128, 384>>>(c0);
    k_projmma<<<TT, 256>>>(bout);
    k_viterbi<<<BB, 32>>>(trans, out);
}